// round 12
// baseline (speedup 1.0000x reference)
#include <cuda_runtime.h>
#include <cuda_bf16.h>

// PathSampling, warp-per-node + cache-policy split (streaming = evict-first).
// R12: 512-thr blocks (occupancy tail), slot->src map via 2x __reduce_or_sync
// instead of 8 ballots (packs source lane into 5-bit fields keyed by rank).

__global__ __launch_bounds__(512) void path_sampling_kernel(
    const int*   __restrict__ paths,      // [n_node, 32, 8]
    const int*   __restrict__ edge_ids,   // [n_node, 32, 7]
    const int*   __restrict__ rand_lens,  // [n_node, 32]
    const float* __restrict__ centrality, // [n_graph]
    float*       __restrict__ out_paths,  // [n_node, 8, 8] float32
    float*       __restrict__ out_edges,  // [n_node, 8, 7] float32
    int n_node)
{
    const int warp_id = (blockIdx.x * blockDim.x + threadIdx.x) >> 5;
    const int lane    = threadIdx.x & 31;
    if (warp_id >= n_node) return;
    const long long node = warp_id;

    // ---- streaming loads: evict-first so they don't churn L1D ----
    const int4* prow = reinterpret_cast<const int4*>(paths + (node * 32 + lane) * 8);
    int4 p0 = __ldcs(prow + 0);
    int4 p1 = __ldcs(prow + 1);
    const int len = __ldcs(rand_lens + node * 32 + lane);

    int mp[8] = {p0.x, p0.y, p0.z, p0.w, p1.x, p1.y, p1.z, p1.w};

    // ---- mask (pos > len -> -1) + score; gathers keep normal caching ----
    float score = 0.0f;
#pragma unroll
    for (int j = 0; j < 8; j++) {
        if (j > len) {
            mp[j] = -1;
        } else {
            score += __ldg(centrality + mp[j]);
        }
    }

    // ---- stable rank among 32 lanes: higher score first, tie -> lower lane ----
    int rank = 0;
#pragma unroll
    for (int j = 0; j < 32; j++) {
        float sj = __shfl_sync(0xffffffffu, score, j);
        rank += (sj > score) || (sj == score && j < lane);
    }

    // ---- slot -> source lane map via 2x OR-reduction (5-bit fields) ----
    // lo holds slots 0..5 (bits 5r..5r+4), hi holds slots 6..7.
    unsigned lo = 0, hi = 0;
    if (rank < 6)                  lo = (unsigned)lane << (rank * 5);
    else if (rank < 8)             hi = (unsigned)lane << ((rank - 6) * 5);
    lo = __reduce_or_sync(0xffffffffu, lo);
    hi = __reduce_or_sync(0xffffffffu, hi);
    // my_src: for lane r<8, the source lane whose rank == r.
    int my_src = (lane < 6) ? (int)((lo >> (lane * 5)) & 31)
                            : (int)((hi >> (((lane - 6) & 1) * 5)) & 31);

    // ---- selected lanes write their path row (float32, evict-first) ----
    if (rank < 8) {
        float4* op = reinterpret_cast<float4*>(out_paths + (node * 8 + rank) * 8);
        __stcs(op + 0, make_float4((float)mp[0], (float)mp[1], (float)mp[2], (float)mp[3]));
        __stcs(op + 1, make_float4((float)mp[4], (float)mp[5], (float)mp[6], (float)mp[7]));
    }

    // ---- warp-cooperative edge copy: 56 contiguous floats/node ----
    const int* ebase = edge_ids + node * (32 * 7);
    float*     obase = out_edges + node * 56;
#pragma unroll
    for (int pass = 0; pass < 2; pass++) {
        int e = lane + pass * 32;
        int s = e / 7;                    // slot 0..7 for active elements
        int j = e - s * 7;
        int src = __shfl_sync(0xffffffffu, my_src, s & 7);
        if (e < 56) {
            __stcs(obase + e, (float)__ldcs(ebase + src * 7 + j));
        }
    }
}

extern "C" void kernel_launch(void* const* d_in, const int* in_sizes, int n_in,
                              void* d_out, int out_size) {
    // Bind inputs by DESCENDING element count (all distinct, order-agnostic):
    //   paths 25.6M > edge_ids 22.4M > rand_lens 3.2M > centrality 100K;
    //   size-1 k_path scalar ignored (constant 8).
    int idx[8];
    int m = 0;
    for (int i = 0; i < n_in && m < 8; i++) {
        if (in_sizes[i] > 1) idx[m++] = i;
    }
    for (int a = 1; a < m; a++) {
        int v = idx[a];
        int b = a - 1;
        while (b >= 0 && in_sizes[idx[b]] < in_sizes[v]) { idx[b + 1] = idx[b]; b--; }
        idx[b + 1] = v;
    }

    const int*   paths      = (const int*)  d_in[idx[0]];
    const int*   edge_ids   = (const int*)  d_in[idx[1]];
    const int*   rand_lens  = (const int*)  d_in[idx[2]];
    const float* centrality = (const float*)d_in[idx[3]];

    const int n_node = in_sizes[idx[0]] / (32 * 8);

    float* out_paths = (float*)d_out;                       // [n_node, 8, 8]
    float* out_edges = out_paths + (long long)n_node * 64;  // [n_node, 8, 7]

    static int configured = -1;
    if (configured < 0) {
        // 0-smem kernel: ask for max L1D carveout explicitly.
        cudaFuncSetAttribute(path_sampling_kernel,
                             cudaFuncAttributePreferredSharedMemoryCarveout, 0);
        configured = 1;
    }

    const int threads = 512;                   // 16 warps -> 16 nodes per block
    const int blocks  = (n_node + 15) / 16;
    path_sampling_kernel<<<blocks, threads>>>(paths, edge_ids, rand_lens,
                                              centrality, out_paths, out_edges,
                                              n_node);
}